// round 15
// baseline (speedup 1.0000x reference)
#include <cuda_runtime.h>
#include <math.h>

#define N_NODES 8192
#define DEG 32
#define N_EDGES (N_NODES*DEG)
#define H 128
#define FULLM 0xffffffffu

// ---------------- device scratch ----------------
__device__ unsigned char g_node_code[N_NODES];
__device__ float g_node_scalars[N_NODES];
__device__ __align__(16) float g_NF[8*H];
__device__ __align__(16) float g_Vnt[8*H];
__device__ float g_ut[8];
__device__ __align__(16) float g_T[36*H];     // T1(16) | T2(16) | T3(4)
__device__ __align__(16) float g_Qt[8*H];     // LN'd
__device__ __align__(16) float g_Knt[8*H];    // LN'd
__device__ __align__(16) float g_Ket[8*H];    // LN'd

// =========================================================================
// kp: 204 blocks x 512 thr
//   blocks 0..39  : node GEMV (m in {Wq,Wk,Wv,gW1,Wek}, c=code) + in-block LN/gate
//   blocks 40..75 : T rows — two chained GEMVs (Wcomb slice, then Wev)
//   blocks 76..203: pre (node codes + self-loop scalars), 64 nodes each (128 blocks)
// =========================================================================
__global__ void __launch_bounds__(512) kp(
    const int* __restrict__ ns,
    const int* __restrict__ src, const float* __restrict__ scalars,
    const float* __restrict__ embV, const float* __restrict__ embR,
    const float* __restrict__ embE, const float* __restrict__ embS,
    const float* __restrict__ Wq, const float* __restrict__ Wk,
    const float* __restrict__ Wv, const float* __restrict__ gW1,
    const float* __restrict__ Wek, const float* __restrict__ Wcomb,
    const float* __restrict__ Wev,
    const float* __restrict__ gb1, const float* __restrict__ gW2,
    const float* __restrict__ gb2,
    const float* __restrict__ qs, const float* __restrict__ qb,
    const float* __restrict__ ks, const float* __restrict__ kb,
    const float* __restrict__ kes, const float* __restrict__ keb)
{
    __shared__ float sP[512];
    __shared__ float sU[128];
    __shared__ float red[8];

    int task = blockIdx.x;
    int tid  = threadIdx.x;
    int h    = tid & 127;
    int kseg = tid >> 7;          // 0..3, 32 k each
    int lane = tid & 31;
    int wid  = tid >> 5;

    if (task >= 76) {
        int bid = task - 76;                  // 0..127
        int n0 = bid * 64 + wid * 4;
        int e0 = n0 * DEG + lane;

        int   sr[4];
        float sc[4];
        #pragma unroll
        for (int r = 0; r < 4; r++) {
            int e = e0 + r * DEG;
            sr[r] = src[e];
            sc[r] = scalars[e];
        }
        #pragma unroll
        for (int r = 0; r < 4; r++) {
            int n = n0 + r;
            float v = (sr[r] == n) ? sc[r] : 0.0f;
            #pragma unroll
            for (int o = 16; o; o >>= 1) v += __shfl_xor_sync(FULLM, v, o);
            if (lane == 0) g_node_scalars[n] = v;
        }
        if (lane < 4) {
            int n = n0 + lane;
            g_node_code[n] = (unsigned char)(ns[3*n] + 2*ns[3*n+1] + 4*ns[3*n+2]);
        }
        return;
    }

    if (task < 40) {
        int m = task >> 3, c = task & 7;
        const float* W;
        switch (m) {
            case 0: W = Wq;  break;
            case 1: W = Wk;  break;
            case 2: W = Wv;  break;
            case 3: W = gW1; break;
            default: W = Wek; break;
        }
        const float* in = ((m == 4) ? embR : embV) + (2*c)*H;
        if (m == 0 && kseg == 0) g_NF[c*H + h] = __ldg(in + h);

        float acc = 0.f;
        {
            const float* Wp = W + (size_t)(kseg*32)*H + h;
            const float* ip = in + kseg*32;
            #pragma unroll
            for (int jj = 0; jj < 32; jj++)
                acc = fmaf(__ldg(ip + jj), __ldg(Wp + (size_t)jj*H), acc);
        }
        sP[tid] = acc;
        __syncthreads();
        float val = 0.f;
        if (kseg == 0)
            val = sP[h] + sP[128 + h] + sP[256 + h] + sP[384 + h];

        if (m == 2) {
            if (kseg == 0) g_Vnt[c*H + h] = val;
            return;
        }
        if (m == 3) {
            if (kseg == 0) {
                float t = fmaxf(val + __ldg(gb1 + h), 0.0f) * __ldg(gW2 + h);
                #pragma unroll
                for (int o = 16; o; o >>= 1) t += __shfl_xor_sync(FULLM, t, o);
                if (lane == 0) red[h >> 5] = t;
            }
            __syncthreads();
            if (kseg == 0 && h == 0) {
                float dot = red[0] + red[1] + red[2] + red[3];
                g_ut[c] = 1.0f / (1.0f + expf(-(dot + __ldg(gb2))));
            }
            return;
        }
        // LN for m in {0(Q),1(K),4(KE)}
        if (kseg == 0) {
            float t = val;
            #pragma unroll
            for (int o = 16; o; o >>= 1) t += __shfl_xor_sync(FULLM, t, o);
            if (lane == 0) red[h >> 5] = t;
        }
        __syncthreads();
        float mu = (red[0] + red[1] + red[2] + red[3]) * (1.0f/H);
        if (kseg == 0) {
            float d = val - mu;
            float t = d*d;
            #pragma unroll
            for (int o = 16; o; o >>= 1) t += __shfl_xor_sync(FULLM, t, o);
            if (lane == 0) red[4 + (h >> 5)] = t;
        }
        __syncthreads();
        if (kseg == 0) {
            float var = (red[4] + red[5] + red[6] + red[7]) * (1.0f/H);
            float rs = rsqrtf(var + 1e-5f);
            float d = val - mu;
            const float* sA; const float* sB; float* out;
            if (m == 0)      { sA = qs;  sB = qb;  out = g_Qt;  }
            else if (m == 1) { sA = ks;  sB = kb;  out = g_Knt; }
            else             { sA = kes; sB = keb; out = g_Ket; }
            out[c*H + h] = d * rs * __ldg(sA + h) + __ldg(sB + h);
        }
        return;
    }

    // ---- T rows (tasks 40..75): U = in @ Wcomb_slice; T = U @ Wev ----
    {
        int r = task - 40;
        int rowoff = (r < 16) ? 0 : (r < 32 ? H : 2*H);
        const float* W = Wcomb + (size_t)rowoff * H;
        const float* in = (r < 32) ? (embE + (r & 15)*H) : (embS + (r - 32)*H);

        float acc = 0.f;
        {
            const float* Wp = W + (size_t)(kseg*32)*H + h;
            const float* ip = in + kseg*32;
            #pragma unroll
            for (int jj = 0; jj < 32; jj++)
                acc = fmaf(__ldg(ip + jj), __ldg(Wp + (size_t)jj*H), acc);
        }
        sP[tid] = acc;
        __syncthreads();
        if (kseg == 0)
            sU[h] = sP[h] + sP[128 + h] + sP[256 + h] + sP[384 + h];
        __syncthreads();

        float acc2 = 0.f;
        {
            const float* wp = Wev + (size_t)(kseg*32)*H + h;
            const float* up = sU + kseg*32;
            #pragma unroll
            for (int jj = 0; jj < 32; jj++)
                acc2 = fmaf(up[jj], __ldg(wp + (size_t)jj*H), acc2);
        }
        __syncthreads();
        sP[tid] = acc2;
        __syncthreads();
        if (kseg == 0)
            g_T[r*H + h] = sP[h] + sP[128 + h] + sP[256 + h] + sP[384 + h];
    }
}

// ================= k_main: warp per node, fused (16 warps, grid 512) ===
// Launched with Programmatic Dependent Launch: all kp-independent loads are
// issued BEFORE cudaGridDependencySynchronize(), overlapping kp's execution.
__global__ void __launch_bounds__(512) k_main(
    const int* __restrict__ src, const float* __restrict__ scalars,
    const int* __restrict__ rev, const int* __restrict__ es,
    const float* __restrict__ embE,
    float* __restrict__ out_node, float* __restrict__ out_edge)
{
    __shared__ __align__(16) float sV[8*H];
    __shared__ __align__(16) float sT[36*H];
    __shared__ __align__(16) float sNF[8*H];
    __shared__ __align__(16) float sEF[16*H];
    __shared__ float sD[64], sDself[8], sut[8];
    __shared__ float sL[16][36];
    __shared__ float sZ[16][36];

    int tid = threadIdx.x;
    int wid = tid >> 5;
    int lane = tid & 31;

    // ---- PDL phase 1: loads independent of kp ----
    int n = blockIdx.x * 16 + wid;
    int e = n * DEG + lane;
    int s  = src[e];
    int re = rev[e];
    int4 ev  = *(const int4*)(es + 4*e);    // coalesced
    int4 evr = *(const int4*)(es + 4*re);   // random gather
    float sc = scalars[e];
    for (int i = tid; i < 16*H; i += 512) sEF[i] = embE[i];

#if __CUDA_ARCH__ >= 900
    cudaGridDependencySynchronize();
#endif

    // ---- PDL phase 2: kp-dependent table loads ----
    for (int i = tid; i < 8*H;  i += 512) { sV[i] = g_Vnt[i]; sNF[i] = g_NF[i]; }
    for (int i = tid; i < 36*H; i += 512) sT[i] = g_T[i];
    if (tid < 8) sut[tid] = g_ut[tid];

    // ---- D table in-block: 72 dots of length 128, warp per dot ----
    {
        const float inv = 0.08838834764831843f; // 1/sqrt(128)
        for (int dd = wid; dd < 72; dd += 16) {
            float acc = 0.f;
            if (dd < 64) {
                int cq = dd >> 3, ck = dd & 7;
                #pragma unroll
                for (int u = 0; u < 4; u++) {
                    int j = lane*4 + u;
                    acc = fmaf(g_Qt[cq*H + j], g_Knt[ck*H + j] + g_Ket[ck*H + j], acc);
                }
            } else {
                int c = dd - 64;
                #pragma unroll
                for (int u = 0; u < 4; u++) {
                    int j = lane*4 + u;
                    acc = fmaf(g_Qt[c*H + j], g_Knt[c*H + j], acc);
                }
            }
            #pragma unroll
            for (int o = 16; o; o >>= 1) acc += __shfl_xor_sync(FULLM, acc, o);
            if (lane == 0) {
                if (dd < 64) sD[dd] = acc * inv;
                else         sDself[dd - 64] = acc * inv;
            }
        }
    }
    __syncthreads();

    int cn = g_node_code[n];
    int cs = g_node_code[s];
    int ce = ev.x  + 2*ev.y  + 4*ev.z  + 8*ev.w;
    int cr = evr.x + 2*evr.y + 4*evr.z + 8*evr.w;
    float recv = g_node_scalars[n];
    float ss   = g_node_scalars[s];
    int st = (sc < recv ? 1 : 0) + ((ss + sc) < recv ? 2 : 0);

    float li    = sD[cn*8 + cs];
    float lself = sDself[cn];

    sL[wid][lane] = li;
    __syncwarp();

    int r = (lself >= li) ? 1 : 0;
    #pragma unroll 8
    for (int j = 0; j < 32; j++) {
        float lj = sL[wid][j];
        r += (lj > li) || (lj == li && j < lane);
    }
    sZ[wid][r] = li;
    unsigned bs = __ballot_sync(FULLM, li > lself);
    if (lane == 0) sZ[wid][__popc(bs)] = lself;
    __syncwarp();

    float zk  = sZ[wid][lane];
    float z32 = sZ[wid][32];

    float cz = zk, cz2 = zk*zk;
    #pragma unroll
    for (int o = 1; o < 32; o <<= 1) {
        float a = __shfl_up_sync(FULLM, cz,  o);
        float b = __shfl_up_sync(FULLM, cz2, o);
        if (lane >= o) { cz += a; cz2 += b; }
    }

    float kk  = (float)(lane + 1);
    float mz  = cz / kk, mz2 = cz2 / kk;
    float dis = fmaxf(mz*mz - mz2 + 1.0f/kk, 0.0f);
    float tauc = mz - sqrtf(dis + 1e-8f);
    int c15 = __popc(__ballot_sync(FULLM, zk > tauc));
    int csp = __popc(__ballot_sync(FULLM, kk*zk > cz - 1.0f));

    float czT  = __shfl_sync(FULLM, cz, 31) + z32;
    float cz2T = __shfl_sync(FULLM, cz2, 31) + z32*z32;
    float mzT  = czT * (1.0f/33.0f), mz2T = cz2T * (1.0f/33.0f);
    float disT = fmaxf(mzT*mzT - mz2T + 1.0f/33.0f, 0.0f);
    float tauc33 = mzT - sqrtf(disT + 1e-8f);
    c15 += (z32 > tauc33) ? 1 : 0;
    csp += (33.0f*z32 > czT - 1.0f) ? 1 : 0;

    float tau15 = (c15 <= 32) ? __shfl_sync(FULLM, tauc, c15 - 1) : tauc33;
    float czat  = (csp <= 32) ? __shfl_sync(FULLM, cz,   csp - 1) : czT;
    float tauSp = (czat - 1.0f) / (float)csp;

    float zmax = sZ[wid][0];
    float ex = expf(li - zmax);
    float se = ex;
    #pragma unroll
    for (int o = 16; o; o >>= 1) se += __shfl_xor_sync(FULLM, se, o);
    float exs = expf(lself - zmax);
    se += exs;

    float u = sut[cn];
    float wlo = 2.0f*u, whi = (u - 0.5f)*2.0f;
    bool lowside = (u <= 0.5f);

    float r15 = fmaxf(li - tau15, 0.0f);
    float p15 = r15*r15;
    float psp = fmaxf(li - tauSp, 0.0f);
    float pso = ex / se;
    float p = lowside ? ((1.0f - wlo)*pso + wlo*p15)
                      : ((1.0f - whi)*p15 + whi*psp);
    bool sel = p > 1e-4f;

    float r15s = fmaxf(lself - tau15, 0.0f);
    float p15s = r15s*r15s;
    float psps = fmaxf(lself - tauSp, 0.0f);
    float psos = exs / se;
    float pS = lowside ? ((1.0f - wlo)*psos + wlo*p15s)
                       : ((1.0f - whi)*p15s + whi*psps);
    bool s0 = pS > 1e-4f;

    int nsel = __popc(__ballot_sync(FULLM, sel)) + (s0 ? 1 : 0);
    float scale = 1.0f / ((float)nsel + 1e-9f);

    float4 agg = make_float4(0.f, 0.f, 0.f, 0.f);
    const float4* V4  = (const float4*)sV;
    const float4* T4  = (const float4*)sT;

    #pragma unroll
    for (int b = 0; b < 8; b++) {
        int c = __popc(__ballot_sync(FULLM, sel && (cs == b))) + ((s0 && cn == b) ? 1 : 0);
        if (c) {
            float fc = (float)c;
            float4 v = V4[b*32 + lane];
            agg.x = fmaf(fc, v.x, agg.x); agg.y = fmaf(fc, v.y, agg.y);
            agg.z = fmaf(fc, v.z, agg.z); agg.w = fmaf(fc, v.w, agg.w);
        }
    }
    #pragma unroll
    for (int b = 0; b < 16; b++) {
        int c = __popc(__ballot_sync(FULLM, sel && (ce == b)));
        if (c) {
            float fc = (float)c;
            float4 v = T4[b*32 + lane];
            agg.x = fmaf(fc, v.x, agg.x); agg.y = fmaf(fc, v.y, agg.y);
            agg.z = fmaf(fc, v.z, agg.z); agg.w = fmaf(fc, v.w, agg.w);
        }
    }
    #pragma unroll
    for (int b = 0; b < 16; b++) {
        int c = __popc(__ballot_sync(FULLM, sel && (cr == b)));
        if (c) {
            float fc = (float)c;
            float4 v = T4[(16 + b)*32 + lane];
            agg.x = fmaf(fc, v.x, agg.x); agg.y = fmaf(fc, v.y, agg.y);
            agg.z = fmaf(fc, v.z, agg.z); agg.w = fmaf(fc, v.w, agg.w);
        }
    }
    #pragma unroll
    for (int b = 0; b < 4; b++) {
        int c = __popc(__ballot_sync(FULLM, sel && (st == b)));
        if (c) {
            float fc = (float)c;
            float4 v = T4[(32 + b)*32 + lane];
            agg.x = fmaf(fc, v.x, agg.x); agg.y = fmaf(fc, v.y, agg.y);
            agg.z = fmaf(fc, v.z, agg.z); agg.w = fmaf(fc, v.w, agg.w);
        }
    }
    agg.x *= scale; agg.y *= scale; agg.z *= scale; agg.w *= scale;

    const float4* NF4 = (const float4*)sNF;
    float4 nf = NF4[cn*32 + lane];
    __stcs(((float4*)out_node) + n*32 + lane,
           make_float4(nf.x + agg.x, nf.y + agg.y, nf.z + agg.z, nf.w + agg.w));

    const float4* EF4 = (const float4*)sEF;
    float4* OE = (float4*)out_edge;
    size_t base = (size_t)n * DEG * 32;
    #pragma unroll 8
    for (int j = 0; j < DEG; j++) {
        int cej = __shfl_sync(FULLM, ce, j);
        float4 ef = EF4[cej*32 + lane];
        __stcs(OE + base + (size_t)j*32 + lane,
               make_float4(ef.x + agg.x, ef.y + agg.y, ef.z + agg.z, ef.w + agg.w));
    }
}

// ---------------- launcher ----------------
extern "C" void kernel_launch(void* const* d_in, const int* in_sizes, int n_in,
                              void* d_out, int out_size)
{
    const int*   node_states = (const int*)  d_in[0];
    const int*   edge_states = (const int*)  d_in[1];
    const float* scalars     = (const float*)d_in[2];
    const int*   edge_index  = (const int*)  d_in[3];
    const int*   rev         = (const int*)  d_in[4];
    int b = 5;
    if (n_in > 5 && in_sizes[5] == 1) b = 6;  // skip training_step if present
    const float* embV  = (const float*)d_in[b + 0];
    const float* embR  = (const float*)d_in[b + 1];
    const float* embE  = (const float*)d_in[b + 2];
    const float* embS  = (const float*)d_in[b + 3];
    const float* Wq    = (const float*)d_in[b + 4];
    const float* Wk    = (const float*)d_in[b + 5];
    const float* Wv    = (const float*)d_in[b + 6];
    const float* Wek   = (const float*)d_in[b + 7];
    const float* Wev   = (const float*)d_in[b + 8];
    const float* Wcomb = (const float*)d_in[b + 9];
    const float* gW1   = (const float*)d_in[b + 10];
    const float* gb1   = (const float*)d_in[b + 11];
    const float* gW2   = (const float*)d_in[b + 12];
    const float* gb2   = (const float*)d_in[b + 13];
    const float* lqs   = (const float*)d_in[b + 14];
    const float* lqb   = (const float*)d_in[b + 15];
    const float* lks   = (const float*)d_in[b + 16];
    const float* lkb   = (const float*)d_in[b + 17];
    const float* lkes  = (const float*)d_in[b + 18];
    const float* lkeb  = (const float*)d_in[b + 19];

    float* out = (float*)d_out;
    float* out_edge = out + (size_t)N_NODES * H;
    const int* src = edge_index;  // row 0 of (2,E)

    kp<<<204, 512>>>(node_states, src, scalars,
                     embV, embR, embE, embS,
                     Wq, Wk, Wv, gW1, Wek, Wcomb, Wev,
                     gb1, gW2, gb2, lqs, lqb, lks, lkb, lkes, lkeb);

    // k_main with Programmatic Dependent Launch: may begin while kp runs;
    // correctness gated by cudaGridDependencySynchronize() inside.
    cudaLaunchConfig_t cfg = {};
    cfg.gridDim  = dim3(N_NODES / 16);
    cfg.blockDim = dim3(512);
    cudaLaunchAttribute attrs[1];
    attrs[0].id = cudaLaunchAttributeProgrammaticStreamSerialization;
    attrs[0].val.programmaticStreamSerializationAllowed = 1;
    cfg.attrs = attrs;
    cfg.numAttrs = 1;
    cudaLaunchKernelEx(&cfg, k_main,
                       src, scalars, rev, edge_states, embE, out, out_edge);
}

// round 16
// speedup vs baseline: 1.0786x; 1.0786x over previous
#include <cuda_runtime.h>
#include <math.h>

#define N_NODES 8192
#define DEG 32
#define N_EDGES (N_NODES*DEG)
#define H 128
#define FULLM 0xffffffffu

// ---------------- device scratch ----------------
__device__ unsigned char g_node_code[N_NODES];
__device__ float g_node_scalars[N_NODES];
__device__ __align__(16) float g_NF[8*H];
__device__ __align__(16) float g_Vnt[8*H];
__device__ float g_ut[8];
__device__ __align__(16) float g_T[36*H];     // T1(16) | T2(16) | T3(4)
__device__ __align__(16) float g_Qt[8*H];     // LN'd
__device__ __align__(16) float g_Knt[8*H];    // LN'd
__device__ __align__(16) float g_Ket[8*H];    // LN'd

// =========================================================================
// kp: 204 blocks x 512 thr  (unchanged from R13/R14 winner)
// =========================================================================
__global__ void __launch_bounds__(512) kp(
    const int* __restrict__ ns,
    const int* __restrict__ src, const float* __restrict__ scalars,
    const float* __restrict__ embV, const float* __restrict__ embR,
    const float* __restrict__ embE, const float* __restrict__ embS,
    const float* __restrict__ Wq, const float* __restrict__ Wk,
    const float* __restrict__ Wv, const float* __restrict__ gW1,
    const float* __restrict__ Wek, const float* __restrict__ Wcomb,
    const float* __restrict__ Wev,
    const float* __restrict__ gb1, const float* __restrict__ gW2,
    const float* __restrict__ gb2,
    const float* __restrict__ qs, const float* __restrict__ qb,
    const float* __restrict__ ks, const float* __restrict__ kb,
    const float* __restrict__ kes, const float* __restrict__ keb)
{
    __shared__ float sP[512];
    __shared__ float sU[128];
    __shared__ float red[8];

    int task = blockIdx.x;
    int tid  = threadIdx.x;
    int h    = tid & 127;
    int kseg = tid >> 7;
    int lane = tid & 31;
    int wid  = tid >> 5;

    if (task >= 76) {
        int bid = task - 76;                  // 0..127
        int n0 = bid * 64 + wid * 4;
        int e0 = n0 * DEG + lane;

        int   sr[4];
        float sc[4];
        #pragma unroll
        for (int r = 0; r < 4; r++) {
            int e = e0 + r * DEG;
            sr[r] = src[e];
            sc[r] = scalars[e];
        }
        #pragma unroll
        for (int r = 0; r < 4; r++) {
            int n = n0 + r;
            float v = (sr[r] == n) ? sc[r] : 0.0f;
            #pragma unroll
            for (int o = 16; o; o >>= 1) v += __shfl_xor_sync(FULLM, v, o);
            if (lane == 0) g_node_scalars[n] = v;
        }
        if (lane < 4) {
            int n = n0 + lane;
            g_node_code[n] = (unsigned char)(ns[3*n] + 2*ns[3*n+1] + 4*ns[3*n+2]);
        }
        return;
    }

    if (task < 40) {
        int m = task >> 3, c = task & 7;
        const float* W;
        switch (m) {
            case 0: W = Wq;  break;
            case 1: W = Wk;  break;
            case 2: W = Wv;  break;
            case 3: W = gW1; break;
            default: W = Wek; break;
        }
        const float* in = ((m == 4) ? embR : embV) + (2*c)*H;
        if (m == 0 && kseg == 0) g_NF[c*H + h] = __ldg(in + h);

        float acc = 0.f;
        {
            const float* Wp = W + (size_t)(kseg*32)*H + h;
            const float* ip = in + kseg*32;
            #pragma unroll
            for (int jj = 0; jj < 32; jj++)
                acc = fmaf(__ldg(ip + jj), __ldg(Wp + (size_t)jj*H), acc);
        }
        sP[tid] = acc;
        __syncthreads();
        float val = 0.f;
        if (kseg == 0)
            val = sP[h] + sP[128 + h] + sP[256 + h] + sP[384 + h];

        if (m == 2) {
            if (kseg == 0) g_Vnt[c*H + h] = val;
            return;
        }
        if (m == 3) {
            if (kseg == 0) {
                float t = fmaxf(val + __ldg(gb1 + h), 0.0f) * __ldg(gW2 + h);
                #pragma unroll
                for (int o = 16; o; o >>= 1) t += __shfl_xor_sync(FULLM, t, o);
                if (lane == 0) red[h >> 5] = t;
            }
            __syncthreads();
            if (kseg == 0 && h == 0) {
                float dot = red[0] + red[1] + red[2] + red[3];
                g_ut[c] = 1.0f / (1.0f + expf(-(dot + __ldg(gb2))));
            }
            return;
        }
        // LN for m in {0(Q),1(K),4(KE)}
        if (kseg == 0) {
            float t = val;
            #pragma unroll
            for (int o = 16; o; o >>= 1) t += __shfl_xor_sync(FULLM, t, o);
            if (lane == 0) red[h >> 5] = t;
        }
        __syncthreads();
        float mu = (red[0] + red[1] + red[2] + red[3]) * (1.0f/H);
        if (kseg == 0) {
            float d = val - mu;
            float t = d*d;
            #pragma unroll
            for (int o = 16; o; o >>= 1) t += __shfl_xor_sync(FULLM, t, o);
            if (lane == 0) red[4 + (h >> 5)] = t;
        }
        __syncthreads();
        if (kseg == 0) {
            float var = (red[4] + red[5] + red[6] + red[7]) * (1.0f/H);
            float rs = rsqrtf(var + 1e-5f);
            float d = val - mu;
            const float* sA; const float* sB; float* out;
            if (m == 0)      { sA = qs;  sB = qb;  out = g_Qt;  }
            else if (m == 1) { sA = ks;  sB = kb;  out = g_Knt; }
            else             { sA = kes; sB = keb; out = g_Ket; }
            out[c*H + h] = d * rs * __ldg(sA + h) + __ldg(sB + h);
        }
        return;
    }

    // ---- T rows (tasks 40..75): U = in @ Wcomb_slice; T = U @ Wev ----
    {
        int r = task - 40;
        int rowoff = (r < 16) ? 0 : (r < 32 ? H : 2*H);
        const float* W = Wcomb + (size_t)rowoff * H;
        const float* in = (r < 32) ? (embE + (r & 15)*H) : (embS + (r - 32)*H);

        float acc = 0.f;
        {
            const float* Wp = W + (size_t)(kseg*32)*H + h;
            const float* ip = in + kseg*32;
            #pragma unroll
            for (int jj = 0; jj < 32; jj++)
                acc = fmaf(__ldg(ip + jj), __ldg(Wp + (size_t)jj*H), acc);
        }
        sP[tid] = acc;
        __syncthreads();
        if (kseg == 0)
            sU[h] = sP[h] + sP[128 + h] + sP[256 + h] + sP[384 + h];
        __syncthreads();

        float acc2 = 0.f;
        {
            const float* wp = Wev + (size_t)(kseg*32)*H + h;
            const float* up = sU + kseg*32;
            #pragma unroll
            for (int jj = 0; jj < 32; jj++)
                acc2 = fmaf(up[jj], __ldg(wp + (size_t)jj*H), acc2);
        }
        __syncthreads();
        sP[tid] = acc2;
        __syncthreads();
        if (kseg == 0)
            g_T[r*H + h] = sP[h] + sP[128 + h] + sP[256 + h] + sP[384 + h];
    }
}

// ================= k_main: warp per node, NO shared tables, NO block barrier =====
// All table lookups go through L1 (tables are shared by every block on an SM;
// L1D persists across CTAs within a launch). Each warp computes only its own
// D row (9 warp-dots). Warps are fully independent.
__global__ void __launch_bounds__(512) k_main(
    const int* __restrict__ src, const float* __restrict__ scalars,
    const int* __restrict__ rev, const int* __restrict__ es,
    const float* __restrict__ embE,
    float* __restrict__ out_node, float* __restrict__ out_edge)
{
    __shared__ float sL[16][36];
    __shared__ float sZ[16][36];
    __shared__ float sDrow[16][9];   // [warp][b]: D[cn][b] (b<8), [8]=Dself

    int tid = threadIdx.x;
    int wid = tid >> 5;
    int lane = tid & 31;

    int n = blockIdx.x * 16 + wid;
    int e = n * DEG + lane;
    int s  = src[e];
    int re = rev[e];
    int4 ev  = *(const int4*)(es + 4*e);    // coalesced
    int4 evr = *(const int4*)(es + 4*re);   // random gather
    float sc = scalars[e];

    int cn = g_node_code[n];
    int cs = g_node_code[s];
    int ce = ev.x  + 2*ev.y  + 4*ev.z  + 8*ev.w;
    int cr = evr.x + 2*evr.y + 4*evr.z + 8*evr.w;
    float recv = g_node_scalars[n];
    float ss   = g_node_scalars[s];
    int st = (sc < recv ? 1 : 0) + ((ss + sc) < recv ? 2 : 0);

    // ---- per-warp D row: D[cn][b] for b=0..7, plus self ----
    {
        const float inv = 0.08838834764831843f; // 1/sqrt(128)
        float4 q4 = __ldg(((const float4*)g_Qt) + cn*32 + lane);
        #pragma unroll
        for (int b = 0; b < 8; b++) {
            float4 kn = __ldg(((const float4*)g_Knt) + b*32 + lane);
            float4 ke = __ldg(((const float4*)g_Ket) + b*32 + lane);
            float acc = q4.x*(kn.x+ke.x) + q4.y*(kn.y+ke.y)
                      + q4.z*(kn.z+ke.z) + q4.w*(kn.w+ke.w);
            #pragma unroll
            for (int o = 16; o; o >>= 1) acc += __shfl_xor_sync(FULLM, acc, o);
            if (lane == 0) sDrow[wid][b] = acc * inv;
        }
        float4 kn = __ldg(((const float4*)g_Knt) + cn*32 + lane);
        float accs = q4.x*kn.x + q4.y*kn.y + q4.z*kn.z + q4.w*kn.w;
        #pragma unroll
        for (int o = 16; o; o >>= 1) accs += __shfl_xor_sync(FULLM, accs, o);
        if (lane == 0) sDrow[wid][8] = accs * inv;
    }
    __syncwarp();

    float li    = sDrow[wid][cs];
    float lself = sDrow[wid][8];

    sL[wid][lane] = li;
    __syncwarp();

    int r = (lself >= li) ? 1 : 0;
    #pragma unroll 8
    for (int j = 0; j < 32; j++) {
        float lj = sL[wid][j];
        r += (lj > li) || (lj == li && j < lane);
    }
    sZ[wid][r] = li;
    unsigned bsl = __ballot_sync(FULLM, li > lself);
    if (lane == 0) sZ[wid][__popc(bsl)] = lself;
    __syncwarp();

    float zk  = sZ[wid][lane];
    float z32 = sZ[wid][32];

    float cz = zk, cz2 = zk*zk;
    #pragma unroll
    for (int o = 1; o < 32; o <<= 1) {
        float a = __shfl_up_sync(FULLM, cz,  o);
        float b = __shfl_up_sync(FULLM, cz2, o);
        if (lane >= o) { cz += a; cz2 += b; }
    }

    float kk  = (float)(lane + 1);
    float mz  = cz / kk, mz2 = cz2 / kk;
    float dis = fmaxf(mz*mz - mz2 + 1.0f/kk, 0.0f);
    float tauc = mz - sqrtf(dis + 1e-8f);
    int c15 = __popc(__ballot_sync(FULLM, zk > tauc));
    int csp = __popc(__ballot_sync(FULLM, kk*zk > cz - 1.0f));

    float czT  = __shfl_sync(FULLM, cz, 31) + z32;
    float cz2T = __shfl_sync(FULLM, cz2, 31) + z32*z32;
    float mzT  = czT * (1.0f/33.0f), mz2T = cz2T * (1.0f/33.0f);
    float disT = fmaxf(mzT*mzT - mz2T + 1.0f/33.0f, 0.0f);
    float tauc33 = mzT - sqrtf(disT + 1e-8f);
    c15 += (z32 > tauc33) ? 1 : 0;
    csp += (33.0f*z32 > czT - 1.0f) ? 1 : 0;

    float tau15 = (c15 <= 32) ? __shfl_sync(FULLM, tauc, c15 - 1) : tauc33;
    float czat  = (csp <= 32) ? __shfl_sync(FULLM, cz,   csp - 1) : czT;
    float tauSp = (czat - 1.0f) / (float)csp;

    float zmax = sZ[wid][0];
    float ex = expf(li - zmax);
    float se = ex;
    #pragma unroll
    for (int o = 16; o; o >>= 1) se += __shfl_xor_sync(FULLM, se, o);
    float exs = expf(lself - zmax);
    se += exs;

    float u = __ldg(g_ut + cn);
    float wlo = 2.0f*u, whi = (u - 0.5f)*2.0f;
    bool lowside = (u <= 0.5f);

    float r15 = fmaxf(li - tau15, 0.0f);
    float p15 = r15*r15;
    float psp = fmaxf(li - tauSp, 0.0f);
    float pso = ex / se;
    float p = lowside ? ((1.0f - wlo)*pso + wlo*p15)
                      : ((1.0f - whi)*p15 + whi*psp);
    bool sel = p > 1e-4f;

    float r15s = fmaxf(lself - tau15, 0.0f);
    float p15s = r15s*r15s;
    float psps = fmaxf(lself - tauSp, 0.0f);
    float psos = exs / se;
    float pS = lowside ? ((1.0f - wlo)*psos + wlo*p15s)
                       : ((1.0f - whi)*p15s + whi*psps);
    bool s0 = pS > 1e-4f;

    int nsel = __popc(__ballot_sync(FULLM, sel)) + (s0 ? 1 : 0);
    float scale = 1.0f / ((float)nsel + 1e-9f);

    // ---- agg via bin counts; tables read through L1 (hot across blocks) ----
    float4 agg = make_float4(0.f, 0.f, 0.f, 0.f);
    const float4* V4 = (const float4*)g_Vnt;
    const float4* T4 = (const float4*)g_T;

    #pragma unroll
    for (int b = 0; b < 8; b++) {
        int c = __popc(__ballot_sync(FULLM, sel && (cs == b))) + ((s0 && cn == b) ? 1 : 0);
        if (c) {
            float fc = (float)c;
            float4 v = __ldg(V4 + b*32 + lane);
            agg.x = fmaf(fc, v.x, agg.x); agg.y = fmaf(fc, v.y, agg.y);
            agg.z = fmaf(fc, v.z, agg.z); agg.w = fmaf(fc, v.w, agg.w);
        }
    }
    #pragma unroll
    for (int b = 0; b < 16; b++) {
        int c = __popc(__ballot_sync(FULLM, sel && (ce == b)));
        if (c) {
            float fc = (float)c;
            float4 v = __ldg(T4 + b*32 + lane);
            agg.x = fmaf(fc, v.x, agg.x); agg.y = fmaf(fc, v.y, agg.y);
            agg.z = fmaf(fc, v.z, agg.z); agg.w = fmaf(fc, v.w, agg.w);
        }
    }
    #pragma unroll
    for (int b = 0; b < 16; b++) {
        int c = __popc(__ballot_sync(FULLM, sel && (cr == b)));
        if (c) {
            float fc = (float)c;
            float4 v = __ldg(T4 + (16 + b)*32 + lane);
            agg.x = fmaf(fc, v.x, agg.x); agg.y = fmaf(fc, v.y, agg.y);
            agg.z = fmaf(fc, v.z, agg.z); agg.w = fmaf(fc, v.w, agg.w);
        }
    }
    #pragma unroll
    for (int b = 0; b < 4; b++) {
        int c = __popc(__ballot_sync(FULLM, sel && (st == b)));
        if (c) {
            float fc = (float)c;
            float4 v = __ldg(T4 + (32 + b)*32 + lane);
            agg.x = fmaf(fc, v.x, agg.x); agg.y = fmaf(fc, v.y, agg.y);
            agg.z = fmaf(fc, v.z, agg.z); agg.w = fmaf(fc, v.w, agg.w);
        }
    }
    agg.x *= scale; agg.y *= scale; agg.z *= scale; agg.w *= scale;

    float4 nf = __ldg(((const float4*)g_NF) + cn*32 + lane);
    __stcs(((float4*)out_node) + n*32 + lane,
           make_float4(nf.x + agg.x, nf.y + agg.y, nf.z + agg.z, nf.w + agg.w));

    const float4* EF4 = (const float4*)embE;
    float4* OE = (float4*)out_edge;
    size_t base = (size_t)n * DEG * 32;
    #pragma unroll 8
    for (int j = 0; j < DEG; j++) {
        int cej = __shfl_sync(FULLM, ce, j);
        float4 ef = __ldg(EF4 + cej*32 + lane);
        __stcs(OE + base + (size_t)j*32 + lane,
               make_float4(ef.x + agg.x, ef.y + agg.y, ef.z + agg.z, ef.w + agg.w));
    }
}

// ---------------- launcher ----------------
extern "C" void kernel_launch(void* const* d_in, const int* in_sizes, int n_in,
                              void* d_out, int out_size)
{
    const int*   node_states = (const int*)  d_in[0];
    const int*   edge_states = (const int*)  d_in[1];
    const float* scalars     = (const float*)d_in[2];
    const int*   edge_index  = (const int*)  d_in[3];
    const int*   rev         = (const int*)  d_in[4];
    int b = 5;
    if (n_in > 5 && in_sizes[5] == 1) b = 6;  // skip training_step if present
    const float* embV  = (const float*)d_in[b + 0];
    const float* embR  = (const float*)d_in[b + 1];
    const float* embE  = (const float*)d_in[b + 2];
    const float* embS  = (const float*)d_in[b + 3];
    const float* Wq    = (const float*)d_in[b + 4];
    const float* Wk    = (const float*)d_in[b + 5];
    const float* Wv    = (const float*)d_in[b + 6];
    const float* Wek   = (const float*)d_in[b + 7];
    const float* Wev   = (const float*)d_in[b + 8];
    const float* Wcomb = (const float*)d_in[b + 9];
    const float* gW1   = (const float*)d_in[b + 10];
    const float* gb1   = (const float*)d_in[b + 11];
    const float* gW2   = (const float*)d_in[b + 12];
    const float* gb2   = (const float*)d_in[b + 13];
    const float* lqs   = (const float*)d_in[b + 14];
    const float* lqb   = (const float*)d_in[b + 15];
    const float* lks   = (const float*)d_in[b + 16];
    const float* lkb   = (const float*)d_in[b + 17];
    const float* lkes  = (const float*)d_in[b + 18];
    const float* lkeb  = (const float*)d_in[b + 19];

    float* out = (float*)d_out;
    const int* src = edge_index;  // row 0 of (2,E)

    kp<<<204, 512>>>(node_states, src, scalars,
                     embV, embR, embE, embS,
                     Wq, Wk, Wv, gW1, Wek, Wcomb, Wev,
                     gb1, gW2, gb2, lqs, lqb, lks, lkb, lkes, lkeb);
    k_main<<<N_NODES/16, 512>>>(src, scalars, rev, edge_states, embE,
                                out, out + (size_t)N_NODES * H);
}